// round 1
// baseline (speedup 1.0000x reference)
#include <cuda_runtime.h>

#define BB 64
#define SS 4096
#define DD 128
#define NPTS (BB*SS)
#define CHUNKS 16
#define PPB (SS/CHUNKS)

// scratch (allocation-free rule: __device__ globals)
__device__ double g_sumB[BB*DD];   // per-(b,d) sums over S
__device__ float4 g_mean4[DD/4];   // global Lorentz centroid
__device__ double g_fs[DD];        // per-feature sum of x_T
__device__ double g_fq[DD];        // per-feature sum of x_T^2

__device__ __forceinline__ float wsum(float v) {
#pragma unroll
    for (int o = 16; o; o >>= 1) v += __shfl_xor_sync(0xffffffffu, v, o);
    return v;
}

__global__ void k_init() {
    int i = threadIdx.x + blockIdx.x * blockDim.x;
    for (int j = i; j < BB*DD; j += blockDim.x * gridDim.x) g_sumB[j] = 0.0;
    if (i < DD) { g_fs[i] = 0.0; g_fq[i] = 0.0; }
}

// Pass 1: sum over S per (b, d)
__global__ __launch_bounds__(256) void k_sumS(const float4* __restrict__ x4) {
    int b     = blockIdx.x >> 4;
    int chunk = blockIdx.x & 15;
    int warp = threadIdx.x >> 5, lane = threadIdx.x & 31;
    const float4* base = x4 + ((size_t)b * SS + (size_t)chunk * PPB) * 32 + lane;
    float4 acc = make_float4(0.f, 0.f, 0.f, 0.f);
    for (int s = warp; s < PPB; s += 8) {
        float4 v = base[(size_t)s * 32];
        acc.x += v.x; acc.y += v.y; acc.z += v.z; acc.w += v.w;
    }
    __shared__ float sh[8 * 128];
    int o = warp * 128 + lane * 4;
    sh[o] = acc.x; sh[o+1] = acc.y; sh[o+2] = acc.z; sh[o+3] = acc.w;
    __syncthreads();
    if (threadIdx.x < 128) {
        float v = 0.f;
#pragma unroll
        for (int w = 0; w < 8; w++) v += sh[w * 128 + threadIdx.x];
        atomicAdd(&g_sumB[b * 128 + threadIdx.x], (double)v);
    }
}

// Pass 2 (tiny): centroid of per-batch centroids
__global__ __launch_bounds__(1024) void k_centroid() {
    __shared__ float sh1[BB * DD];     // 32 KB: mean1[b][d]
    __shared__ float red[128];
    __shared__ float s_linner;
    int tid = threadIdx.x, warp = tid >> 5, lane = tid & 31;

    // each warp handles 2 batches: normalize avg_b onto hyperboloid
#pragma unroll
    for (int rep = 0; rep < 2; rep++) {
        int b = warp + rep * 32;
        float a[4];
        float lc = 0.f;
#pragma unroll
        for (int j = 0; j < 4; j++) {
            a[j] = (float)(g_sumB[b * 128 + lane * 4 + j] * (1.0 / SS));
            float c = a[j] * a[j];
            if (lane == 0 && j == 0) c = -c;   // linner = -u0^2 + sum_rest
            lc += c;
        }
        lc = wsum(lc);                          // = linner(avg,avg)
        float denom = sqrtf(fmaxf(-lc, 1e-8f));
#pragma unroll
        for (int j = 0; j < 4; j++) sh1[b * 128 + lane * 4 + j] = a[j] / denom;
    }
    __syncthreads();

    float a2 = 0.f;
    if (tid < 128) {
        float s = 0.f;
        for (int b = 0; b < BB; b++) s += sh1[b * 128 + tid];
        a2 = s * (1.f / BB);
        float c = a2 * a2;
        red[tid] = (tid == 0) ? -c : c;
    }
    __syncthreads();
    for (int off = 64; off > 0; off >>= 1) {
        if (tid < off) red[tid] += red[tid + off];
        __syncthreads();
    }
    if (tid == 0) s_linner = red[0];
    __syncthreads();
    if (tid < 128) {
        float denom2 = sqrtf(fmaxf(-s_linner, 1e-8f));
        ((float*)g_mean4)[tid] = a2 / denom2;
    }
}

// shared helper: compute x_T (logmap at mean + transport to origin) for point p
__device__ __forceinline__ float4 compute_xT(float4 v, float4 m, float m0,
                                             float inv1pm0, int lane) {
    float dp = wsum(v.x*m.x + v.y*m.y + v.z*m.z + v.w*m.w);
    float x0 = __shfl_sync(0xffffffffu, v.x, 0);
    float alpha = fmaxf(fmaf(2.f*m0, x0, -dp), 1.0f + 1e-7f);
    float4 u;
    u.x = fmaf(-alpha, m.x, v.x);
    u.y = fmaf(-alpha, m.y, v.y);
    u.z = fmaf(-alpha, m.z, v.z);
    u.w = fmaf(-alpha, m.w, v.w);
    float uu = wsum(u.x*u.x + u.y*u.y + u.z*u.z + u.w*u.w);
    float u0 = __shfl_sync(0xffffffffu, u.x, 0);
    float uul = fmaxf(uu - 2.f*u0*u0, 1e-8f);
    float fac = acoshf(alpha) * rsqrtf(uul);
    float xt0 = fac * u0;
    float coef = -xt0 * inv1pm0;                 // transp0back
    float4 t;
    t.x = fmaf(fac, u.x, coef * (m.x + (lane == 0 ? 1.f : 0.f)));
    t.y = fmaf(fac, u.y, coef * m.y);
    t.z = fmaf(fac, u.z, coef * m.z);
    t.w = fmaf(fac, u.w, coef * m.w);
    return t;
}

// Pass 3: per-feature sum / sumsq of x_T
__global__ __launch_bounds__(256) void k_stats(const float4* __restrict__ x4) {
    int warp = threadIdx.x >> 5, lane = threadIdx.x & 31;
    float4 m = g_mean4[lane];
    float m0 = __shfl_sync(0xffffffffu, m.x, 0);
    float inv1pm0 = 1.f / (1.f + m0);
    float4 ss = make_float4(0,0,0,0), sq = make_float4(0,0,0,0);
    int gw = blockIdx.x * 8 + warp;
    int nw = gridDim.x * 8;
    for (int p = gw; p < NPTS; p += nw) {
        float4 v = x4[(size_t)p * 32 + lane];
        float4 t = compute_xT(v, m, m0, inv1pm0, lane);
        ss.x += t.x; ss.y += t.y; ss.z += t.z; ss.w += t.w;
        sq.x = fmaf(t.x, t.x, sq.x); sq.y = fmaf(t.y, t.y, sq.y);
        sq.z = fmaf(t.z, t.z, sq.z); sq.w = fmaf(t.w, t.w, sq.w);
    }
    __shared__ float shs[8 * 128];
    __shared__ float shq[8 * 128];
    int o = warp * 128 + lane * 4;
    shs[o]=ss.x; shs[o+1]=ss.y; shs[o+2]=ss.z; shs[o+3]=ss.w;
    shq[o]=sq.x; shq[o+1]=sq.y; shq[o+2]=sq.z; shq[o+3]=sq.w;
    __syncthreads();
    if (threadIdx.x < 128) {
        float a = 0.f, b = 0.f;
#pragma unroll
        for (int w = 0; w < 8; w++) { a += shs[w*128 + threadIdx.x]; b += shq[w*128 + threadIdx.x]; }
        atomicAdd(&g_fs[threadIdx.x], (double)a);
        atomicAdd(&g_fq[threadIdx.x], (double)b);
    }
}

// Pass 4: scale, rescale-to-max-euclid, transp0(beta), expmap(beta), write out
__global__ __launch_bounds__(256) void k_final(const float4* __restrict__ x4,
                                               const float4* __restrict__ gamma4,
                                               const float4* __restrict__ beta4,
                                               float4* __restrict__ out4) {
    int warp = threadIdx.x >> 5, lane = threadIdx.x & 31;
    float4 m = g_mean4[lane];
    float m0 = __shfl_sync(0xffffffffu, m.x, 0);
    float inv1pm0 = 1.f / (1.f + m0);

    // per-feature scale = gamma / (sqrt(var + eps) + eps)
    float4 g = gamma4[lane];
    float4 scl;
    {
        float gv[4] = {g.x, g.y, g.z, g.w};
        float sv[4];
#pragma unroll
        for (int j = 0; j < 4; j++) {
            int d = lane * 4 + j;
            float mv  = (float)(g_fs[d] * (1.0 / NPTS));
            float var = (float)(g_fq[d] * (1.0 / NPTS)) - mv * mv;
            float std = sqrtf(fmaxf(var, 0.f) + 1e-5f);
            sv[j] = gv[j] / (std + 1e-5f);
        }
        scl = make_float4(sv[0], sv[1], sv[2], sv[3]);
    }
    float4 be = beta4[lane];
    float b0 = __shfl_sync(0xffffffffu, be.x, 0);
    float inv1pb0 = 1.f / (1.f + b0);

    int gw = blockIdx.x * 8 + warp;
    int nw = gridDim.x * 8;
    for (int p = gw; p < NPTS; p += nw) {
        float4 v = x4[(size_t)p * 32 + lane];
        float4 t = compute_xT(v, m, m0, inv1pm0, lane);
        t.x *= scl.x; t.y *= scl.y; t.z *= scl.z; t.w *= scl.w;

        // rescale to max euclid norm 32
        float nn = wsum(t.x*t.x + t.y*t.y + t.z*t.z + t.w*t.w);
        float en = sqrtf(nn);
        float esc = fminf(1.f, 32.f / fmaxf(en, 1e-8f));
        t.x *= esc; t.y *= esc; t.z *= esc; t.w *= esc;

        // transp0(beta, t)
        float db = wsum(t.x*be.x + t.y*be.y + t.z*be.z + t.w*be.w);
        float t0 = __shfl_sync(0xffffffffu, t.x, 0);
        float coef = (db - 2.f*b0*t0) * inv1pb0;
        t.x = fmaf(coef, be.x + (lane == 0 ? 1.f : 0.f), t.x);
        t.y = fmaf(coef, be.y, t.y);
        t.z = fmaf(coef, be.z, t.z);
        t.w = fmaf(coef, be.w, t.w);

        // expmap(beta, t)
        float nn2 = wsum(t.x*t.x + t.y*t.y + t.z*t.z + t.w*t.w);
        float t0b = __shfl_sync(0xffffffffu, t.x, 0);
        float nu2 = fmaxf(nn2 - 2.f*t0b*t0b, 1e-8f);
        float nu = sqrtf(nu2);
        float ch = coshf(nu);
        float sh = sinhf(nu) / nu;
        float4 o;
        o.x = fmaf(ch, be.x, sh * t.x);
        o.y = fmaf(ch, be.y, sh * t.y);
        o.z = fmaf(ch, be.z, sh * t.z);
        o.w = fmaf(ch, be.w, sh * t.w);
        out4[(size_t)p * 32 + lane] = o;
    }
}

extern "C" void kernel_launch(void* const* d_in, const int* in_sizes, int n_in,
                              void* d_out, int out_size) {
    const float4* x  = (const float4*)d_in[0];
    const float4* ga = (const float4*)d_in[1];
    const float4* be = (const float4*)d_in[2];
    float4* out = (float4*)d_out;
    (void)in_sizes; (void)n_in; (void)out_size;

    k_init<<<8, 1024>>>();
    k_sumS<<<BB * CHUNKS, 256>>>(x);
    k_centroid<<<1, 1024>>>();
    k_stats<<<1216, 256>>>(x);
    k_final<<<1216, 256>>>(x, ga, be, out);
}

// round 2
// speedup vs baseline: 1.1025x; 1.1025x over previous
#include <cuda_runtime.h>

#define BB 64
#define SS 4096
#define DD 128
#define NPTS (BB*SS)
#define CHUNKS 16
#define PPB (SS/CHUNKS)

// scratch (allocation-free rule: __device__ globals)
__device__ double g_sumB[BB*DD];   // per-(b,d) sums over S
__device__ float4 g_mean4[DD/4];   // global Lorentz centroid
__device__ double g_fs[DD];        // per-feature sum of x_T
__device__ double g_fq[DD];        // per-feature sum of x_T^2

__device__ __forceinline__ float wsum(float v) {
#pragma unroll
    for (int o = 16; o; o >>= 1) v += __shfl_xor_sync(0xffffffffu, v, o);
    return v;
}

// P independent butterfly reductions, interleaved to hide SHFL latency
template<int P>
__device__ __forceinline__ void wsumP(float* v) {
#pragma unroll
    for (int o = 16; o; o >>= 1) {
        float t[P];
#pragma unroll
        for (int i = 0; i < P; i++) t[i] = __shfl_xor_sync(0xffffffffu, v[i], o);
#pragma unroll
        for (int i = 0; i < P; i++) v[i] += t[i];
    }
}

__global__ void k_init() {
    int i = threadIdx.x + blockIdx.x * blockDim.x;
    for (int j = i; j < BB*DD; j += blockDim.x * gridDim.x) g_sumB[j] = 0.0;
    if (i < DD) { g_fs[i] = 0.0; g_fq[i] = 0.0; }
}

// Pass 1: sum over S per (b, d)
__global__ __launch_bounds__(256) void k_sumS(const float4* __restrict__ x4) {
    int b     = blockIdx.x >> 4;
    int chunk = blockIdx.x & 15;
    int warp = threadIdx.x >> 5, lane = threadIdx.x & 31;
    const float4* base = x4 + ((size_t)b * SS + (size_t)chunk * PPB) * 32 + lane;
    float4 acc = make_float4(0.f, 0.f, 0.f, 0.f);
#pragma unroll 4
    for (int s = warp; s < PPB; s += 8) {
        float4 v = base[(size_t)s * 32];
        acc.x += v.x; acc.y += v.y; acc.z += v.z; acc.w += v.w;
    }
    __shared__ float sh[8 * 128];
    int o = warp * 128 + lane * 4;
    sh[o] = acc.x; sh[o+1] = acc.y; sh[o+2] = acc.z; sh[o+3] = acc.w;
    __syncthreads();
    if (threadIdx.x < 128) {
        float v = 0.f;
#pragma unroll
        for (int w = 0; w < 8; w++) v += sh[w * 128 + threadIdx.x];
        atomicAdd(&g_sumB[b * 128 + threadIdx.x], (double)v);
    }
}

// Pass 2 (tiny): centroid of per-batch centroids
__global__ __launch_bounds__(1024) void k_centroid() {
    __shared__ float sh1[BB * DD];
    __shared__ float red[128];
    __shared__ float s_linner;
    int tid = threadIdx.x, warp = tid >> 5, lane = tid & 31;

#pragma unroll
    for (int rep = 0; rep < 2; rep++) {
        int b = warp + rep * 32;
        float a[4];
        float lc = 0.f;
#pragma unroll
        for (int j = 0; j < 4; j++) {
            a[j] = (float)(g_sumB[b * 128 + lane * 4 + j] * (1.0 / SS));
            float c = a[j] * a[j];
            if (lane == 0 && j == 0) c = -c;
            lc += c;
        }
        lc = wsum(lc);
        float denom = sqrtf(fmaxf(-lc, 1e-8f));
#pragma unroll
        for (int j = 0; j < 4; j++) sh1[b * 128 + lane * 4 + j] = a[j] / denom;
    }
    __syncthreads();

    float a2 = 0.f;
    if (tid < 128) {
        float s = 0.f;
        for (int b = 0; b < BB; b++) s += sh1[b * 128 + tid];
        a2 = s * (1.f / BB);
        float c = a2 * a2;
        red[tid] = (tid == 0) ? -c : c;
    }
    __syncthreads();
    for (int off = 64; off > 0; off >>= 1) {
        if (tid < off) red[tid] += red[tid + off];
        __syncthreads();
    }
    if (tid == 0) s_linner = red[0];
    __syncthreads();
    if (tid < 128) {
        float denom2 = sqrtf(fmaxf(-s_linner, 1e-8f));
        ((float*)g_mean4)[tid] = a2 / denom2;
    }
}

// x_T for P points at once: logmap at mean + transport to origin.
// On entry v[i] = x point; on exit v[i] = x_T.
// mxs = sgn*m.x (sgn = -1 on lane 0), e0 = 1 on lane 0 else 0.
template<int P>
__device__ __forceinline__ void xT_P(float4* v, const float4 m, const float mxs,
                                     const float inv1pm0, const float e0, const float sgn) {
    float dp[P];
#pragma unroll
    for (int i = 0; i < P; i++)
        dp[i] = v[i].x*mxs + v[i].y*m.y + v[i].z*m.z + v[i].w*m.w;  // -> linner(x, m)
    wsumP<P>(dp);
    float uu[P];
#pragma unroll
    for (int i = 0; i < P; i++) {
        float alpha = fmaxf(-dp[i], 1.0f + 1e-7f);
        dp[i] = alpha;
        float4 u;
        u.x = fmaf(-alpha, m.x, v[i].x);
        u.y = fmaf(-alpha, m.y, v[i].y);
        u.z = fmaf(-alpha, m.z, v[i].z);
        u.w = fmaf(-alpha, m.w, v[i].w);
        v[i] = u;
        uu[i] = (sgn*u.x)*u.x + u.y*u.y + u.z*u.z + u.w*u.w;  // linner(u,u)
    }
    wsumP<P>(uu);
    float u0[P];
#pragma unroll
    for (int i = 0; i < P; i++) u0[i] = __shfl_sync(0xffffffffu, v[i].x, 0);
#pragma unroll
    for (int i = 0; i < P; i++) {
        float fac = acoshf(dp[i]) * rsqrtf(fmaxf(uu[i], 1e-8f));
        float coef = -fac * u0[i] * inv1pm0;   // transp0back
        float4 u = v[i], t;
        t.x = fmaf(fac, u.x, coef * (m.x + e0));
        t.y = fmaf(fac, u.y, coef * m.y);
        t.z = fmaf(fac, u.z, coef * m.z);
        t.w = fmaf(fac, u.w, coef * m.w);
        v[i] = t;
    }
}

// Pass 3: per-feature sum / sumsq of x_T (P=4 ILP, reversed sweep for L2 reuse)
__global__ __launch_bounds__(256) void k_stats(const float4* __restrict__ x4) {
    constexpr int P = 4;
    constexpr int NWTOT = 8192;                 // 1024 blocks * 8 warps
    constexpr int NITER = NPTS / (NWTOT * P);   // 8
    int warp = threadIdx.x >> 5, lane = threadIdx.x & 31;
    float sgn = (lane == 0) ? -1.f : 1.f;
    float e0  = (lane == 0) ?  1.f : 0.f;
    float4 m = g_mean4[lane];
    float m0 = __shfl_sync(0xffffffffu, m.x, 0);
    float inv1pm0 = 1.f / (1.f + m0);
    float mxs = sgn * m.x;
    int gw = blockIdx.x * 8 + warp;
    float4 ss = make_float4(0,0,0,0), sq = make_float4(0,0,0,0);
    for (int it = NITER - 1; it >= 0; it--) {    // reversed: hit k_sumS's L2 tail
        size_t pbase = (size_t)it * NWTOT * P + (size_t)gw * P;
        float4 v[P];
#pragma unroll
        for (int i = 0; i < P; i++) v[i] = x4[(pbase + i) * 32 + lane];
        xT_P<P>(v, m, mxs, inv1pm0, e0, sgn);
#pragma unroll
        for (int i = 0; i < P; i++) {
            ss.x += v[i].x; ss.y += v[i].y; ss.z += v[i].z; ss.w += v[i].w;
            sq.x = fmaf(v[i].x, v[i].x, sq.x); sq.y = fmaf(v[i].y, v[i].y, sq.y);
            sq.z = fmaf(v[i].z, v[i].z, sq.z); sq.w = fmaf(v[i].w, v[i].w, sq.w);
        }
    }
    __shared__ float shs[8 * 128];
    __shared__ float shq[8 * 128];
    int o = warp * 128 + lane * 4;
    shs[o]=ss.x; shs[o+1]=ss.y; shs[o+2]=ss.z; shs[o+3]=ss.w;
    shq[o]=sq.x; shq[o+1]=sq.y; shq[o+2]=sq.z; shq[o+3]=sq.w;
    __syncthreads();
    if (threadIdx.x < 128) {
        float a = 0.f, b = 0.f;
#pragma unroll
        for (int w = 0; w < 8; w++) { a += shs[w*128 + threadIdx.x]; b += shq[w*128 + threadIdx.x]; }
        atomicAdd(&g_fs[threadIdx.x], (double)a);
        atomicAdd(&g_fq[threadIdx.x], (double)b);
    }
}

// Pass 4: scale, rescale-to-max-euclid, transp0(beta), expmap(beta) (P=2 ILP)
__global__ __launch_bounds__(256) void k_final(const float4* __restrict__ x4,
                                               const float4* __restrict__ gamma4,
                                               const float4* __restrict__ beta4,
                                               float4* __restrict__ out4) {
    constexpr int P = 2;
    constexpr int NWTOT = 8192;
    constexpr int NITER = NPTS / (NWTOT * P);   // 16
    int warp = threadIdx.x >> 5, lane = threadIdx.x & 31;
    float sgn = (lane == 0) ? -1.f : 1.f;
    float e0  = (lane == 0) ?  1.f : 0.f;
    float4 m = g_mean4[lane];
    float m0 = __shfl_sync(0xffffffffu, m.x, 0);
    float inv1pm0 = 1.f / (1.f + m0);
    float mxs = sgn * m.x;

    // per-feature scale = gamma / (sqrt(var + eps) + eps)
    float4 g = gamma4[lane];
    float4 scl;
    {
        float gv[4] = {g.x, g.y, g.z, g.w};
        float sv[4];
#pragma unroll
        for (int j = 0; j < 4; j++) {
            int d = lane * 4 + j;
            float mv  = (float)(g_fs[d] * (1.0 / NPTS));
            float var = (float)(g_fq[d] * (1.0 / NPTS)) - mv * mv;
            float std = sqrtf(fmaxf(var, 0.f) + 1e-5f);
            sv[j] = gv[j] / (std + 1e-5f);
        }
        scl = make_float4(sv[0], sv[1], sv[2], sv[3]);
    }
    float4 be = beta4[lane];
    float b0 = __shfl_sync(0xffffffffu, be.x, 0);
    float inv1pb0 = 1.f / (1.f + b0);
    float bxs = sgn * be.x;

    int gw = blockIdx.x * 8 + warp;
    for (int it = 0; it < NITER; it++) {        // forward: hit k_stats' L2 tail
        size_t pbase = (size_t)it * NWTOT * P + (size_t)gw * P;
        float4 v[P];
#pragma unroll
        for (int i = 0; i < P; i++) v[i] = x4[(pbase + i) * 32 + lane];
        xT_P<P>(v, m, mxs, inv1pm0, e0, sgn);
#pragma unroll
        for (int i = 0; i < P; i++) {
            v[i].x *= scl.x; v[i].y *= scl.y; v[i].z *= scl.z; v[i].w *= scl.w;
        }
        // interleave euclid-norm (r[2i]) and linner(beta, t) (r[2i+1]) reductions
        float r[2 * P];
#pragma unroll
        for (int i = 0; i < P; i++) {
            float4 t = v[i];
            r[2*i]   = t.x*t.x  + t.y*t.y  + t.z*t.z  + t.w*t.w;
            r[2*i+1] = t.x*bxs + t.y*be.y + t.z*be.z + t.w*be.w;
        }
        wsumP<2 * P>(r);
        float q[P];
#pragma unroll
        for (int i = 0; i < P; i++) {
            float en  = sqrtf(r[2*i]);
            float esc = fminf(1.f, 32.f / fmaxf(en, 1e-8f));     // rescale cap
            float coef = r[2*i+1] * inv1pb0;                      // transp0(beta, .)
            float4 t = v[i], w;
            w.x = esc * fmaf(coef, be.x + e0, t.x);
            w.y = esc * fmaf(coef, be.y, t.y);
            w.z = esc * fmaf(coef, be.z, t.z);
            w.w = esc * fmaf(coef, be.w, t.w);
            v[i] = w;
            q[i] = (sgn*w.x)*w.x + w.y*w.y + w.z*w.z + w.w*w.w;   // linner(w,w)
        }
        wsumP<P>(q);
#pragma unroll
        for (int i = 0; i < P; i++) {
            float nu = sqrtf(fmaxf(q[i], 1e-8f));
            float ch = coshf(nu);
            float sh = sinhf(nu) / nu;
            float4 w = v[i], o;
            o.x = fmaf(ch, be.x, sh * w.x);
            o.y = fmaf(ch, be.y, sh * w.y);
            o.z = fmaf(ch, be.z, sh * w.z);
            o.w = fmaf(ch, be.w, sh * w.w);
            __stcs(&out4[(pbase + i) * 32 + lane], o);            // evict-first store
        }
    }
}

extern "C" void kernel_launch(void* const* d_in, const int* in_sizes, int n_in,
                              void* d_out, int out_size) {
    const float4* x  = (const float4*)d_in[0];
    const float4* ga = (const float4*)d_in[1];
    const float4* be = (const float4*)d_in[2];
    float4* out = (float4*)d_out;
    (void)in_sizes; (void)n_in; (void)out_size;

    k_init<<<8, 1024>>>();
    k_sumS<<<BB * CHUNKS, 256>>>(x);
    k_centroid<<<1, 1024>>>();
    k_stats<<<1024, 256>>>(x);
    k_final<<<1024, 256>>>(x, ga, be, out);
}

// round 3
// speedup vs baseline: 1.3449x; 1.2199x over previous
#include <cuda_runtime.h>

#define BB 64
#define SS 4096
#define DD 128
#define NPTS (BB*SS)
#define CHUNKS 16
#define PPB (SS/CHUNKS)
#define GRID_MAIN 1184            // 8 * 148 SMs
#define NWTOT (GRID_MAIN * 8)     // warps in main kernels

// scratch (allocation-free rule: __device__ globals)
__device__ double g_sumB[BB*DD];   // per-(b,d) sums over S
__device__ float4 g_mean4[DD/4];   // global Lorentz centroid
__device__ double g_fs[DD];        // per-feature sum of x_T
__device__ double g_fq[DD];        // per-feature sum of x_T^2

__device__ __forceinline__ float wsum(float v) {
#pragma unroll
    for (int o = 16; o; o >>= 1) v += __shfl_xor_sync(0xffffffffu, v, o);
    return v;
}

template<int P>
__device__ __forceinline__ void wsumP(float* v) {
#pragma unroll
    for (int o = 16; o; o >>= 1) {
        float t[P];
#pragma unroll
        for (int i = 0; i < P; i++) t[i] = __shfl_xor_sync(0xffffffffu, v[i], o);
#pragma unroll
        for (int i = 0; i < P; i++) v[i] += t[i];
    }
}

__global__ void k_init() {
    int i = threadIdx.x + blockIdx.x * blockDim.x;
    for (int j = i; j < BB*DD; j += blockDim.x * gridDim.x) g_sumB[j] = 0.0;
    if (i < DD) { g_fs[i] = 0.0; g_fq[i] = 0.0; }
}

// Pass 1: sum over S per (b, d)
__global__ __launch_bounds__(256) void k_sumS(const float4* __restrict__ x4) {
    int b     = blockIdx.x >> 4;
    int chunk = blockIdx.x & 15;
    int warp = threadIdx.x >> 5, lane = threadIdx.x & 31;
    const float4* base = x4 + ((size_t)b * SS + (size_t)chunk * PPB) * 32 + lane;
    float4 acc = make_float4(0.f, 0.f, 0.f, 0.f);
#pragma unroll 4
    for (int s = warp; s < PPB; s += 8) {
        float4 v = base[(size_t)s * 32];
        acc.x += v.x; acc.y += v.y; acc.z += v.z; acc.w += v.w;
    }
    __shared__ float sh[8 * 128];
    int o = warp * 128 + lane * 4;
    sh[o] = acc.x; sh[o+1] = acc.y; sh[o+2] = acc.z; sh[o+3] = acc.w;
    __syncthreads();
    if (threadIdx.x < 128) {
        float v = 0.f;
#pragma unroll
        for (int w = 0; w < 8; w++) v += sh[w * 128 + threadIdx.x];
        atomicAdd(&g_sumB[b * 128 + threadIdx.x], (double)v);
    }
}

// Pass 2 (tiny): centroid of per-batch centroids
__global__ __launch_bounds__(1024) void k_centroid() {
    __shared__ float sh1[BB * DD];
    __shared__ float red[128];
    __shared__ float s_linner;
    int tid = threadIdx.x, warp = tid >> 5, lane = tid & 31;

#pragma unroll
    for (int rep = 0; rep < 2; rep++) {
        int b = warp + rep * 32;
        float a[4];
        float lc = 0.f;
#pragma unroll
        for (int j = 0; j < 4; j++) {
            a[j] = (float)(g_sumB[b * 128 + lane * 4 + j] * (1.0 / SS));
            float c = a[j] * a[j];
            if (lane == 0 && j == 0) c = -c;
            lc += c;
        }
        lc = wsum(lc);
        float denom = sqrtf(fmaxf(-lc, 1e-8f));
#pragma unroll
        for (int j = 0; j < 4; j++) sh1[b * 128 + lane * 4 + j] = a[j] / denom;
    }
    __syncthreads();

    float a2 = 0.f;
    if (tid < 128) {
        float s = 0.f;
        for (int b = 0; b < BB; b++) s += sh1[b * 128 + tid];
        a2 = s * (1.f / BB);
        float c = a2 * a2;
        red[tid] = (tid == 0) ? -c : c;
    }
    __syncthreads();
    for (int off = 64; off > 0; off >>= 1) {
        if (tid < off) red[tid] += red[tid + off];
        __syncthreads();
    }
    if (tid == 0) s_linner = red[0];
    __syncthreads();
    if (tid < 128) {
        float denom2 = sqrtf(fmaxf(-s_linner, 1e-8f));
        ((float*)g_mean4)[tid] = a2 / denom2;
    }
}

// x_T for P points: logmap at mean + transport to origin. ONE warp reduction.
// Uses hyperboloid identity: linner(u,u) = alpha^2 - 1 (x, m both on hyperboloid),
// and acosh(a) = log(a + sqrt(a^2-1)).
template<int P>
__device__ __forceinline__ void xT_P(float4* v, const float4 m, const float mxs,
                                     const float m0, const float inv1pm0,
                                     const float e0) {
    float dp[P];
#pragma unroll
    for (int i = 0; i < P; i++)
        dp[i] = v[i].x*mxs + v[i].y*m.y + v[i].z*m.z + v[i].w*m.w;  // -> linner(x,m)
    wsumP<P>(dp);
    float x0[P];
#pragma unroll
    for (int i = 0; i < P; i++) x0[i] = __shfl_sync(0xffffffffu, v[i].x, 0);
#pragma unroll
    for (int i = 0; i < P; i++) {
        float alpha  = fmaxf(-dp[i], 1.0f + 1e-7f);
        float uu     = fmaf(alpha, alpha, -1.0f);           // linner(u,u)
        float runorm = rsqrtf(uu);
        float unorm  = uu * runorm;
        float fac    = __logf(alpha + unorm) * runorm;      // acosh(a)/|u|
        float u0     = fmaf(-alpha, m0, x0[i]);
        float coef   = -fac * u0 * inv1pm0;                 // transp0back
        float c2     = coef - fac * alpha;                  // t = fac*x + c2*m + coef*o
        float4 t;
        t.x = fmaf(fac, v[i].x, fmaf(c2, m.x, coef * e0));
        t.y = fmaf(fac, v[i].y, c2 * m.y);
        t.z = fmaf(fac, v[i].z, c2 * m.z);
        t.w = fmaf(fac, v[i].w, c2 * m.w);
        v[i] = t;
    }
}

// Pass 3: per-feature sum / sumsq of x_T
__global__ __launch_bounds__(256) void k_stats(const float4* __restrict__ x4) {
    constexpr int P = 2;
    int warp = threadIdx.x >> 5, lane = threadIdx.x & 31;
    float4 m = g_mean4[lane];
    float m0 = __shfl_sync(0xffffffffu, m.x, 0);
    float inv1pm0 = 1.f / (1.f + m0);
    float mxs = (lane == 0) ? -m.x : m.x;
    float e0  = (lane == 0) ?  1.f : 0.f;
    float4 ss = make_float4(0,0,0,0), sq = make_float4(0,0,0,0);
    int gw = blockIdx.x * 8 + warp;
    for (int p = gw; p < NPTS / P; p += NWTOT) {
        const float4* ptr = x4 + (unsigned)(p * P) * 32u + lane;
        float4 v[P];
#pragma unroll
        for (int i = 0; i < P; i++) v[i] = ptr[i * 32];
        xT_P<P>(v, m, mxs, m0, inv1pm0, e0);
#pragma unroll
        for (int i = 0; i < P; i++) {
            ss.x += v[i].x; ss.y += v[i].y; ss.z += v[i].z; ss.w += v[i].w;
            sq.x = fmaf(v[i].x, v[i].x, sq.x); sq.y = fmaf(v[i].y, v[i].y, sq.y);
            sq.z = fmaf(v[i].z, v[i].z, sq.z); sq.w = fmaf(v[i].w, v[i].w, sq.w);
        }
    }
    __shared__ float shs[8 * 128];
    __shared__ float shq[8 * 128];
    int o = warp * 128 + lane * 4;
    shs[o]=ss.x; shs[o+1]=ss.y; shs[o+2]=ss.z; shs[o+3]=ss.w;
    shq[o]=sq.x; shq[o+1]=sq.y; shq[o+2]=sq.z; shq[o+3]=sq.w;
    __syncthreads();
    if (threadIdx.x < 128) {
        float a = 0.f, b = 0.f;
#pragma unroll
        for (int w = 0; w < 8; w++) { a += shs[w*128 + threadIdx.x]; b += shq[w*128 + threadIdx.x]; }
        atomicAdd(&g_fs[threadIdx.x], (double)a);
        atomicAdd(&g_fq[threadIdx.x], (double)b);
    }
}

// Pass 4: scale, rescale-to-max-euclid, transp0(beta), expmap(beta).
// Transport preserves linner => expmap norm comes from the euclid reduction.
__global__ __launch_bounds__(256) void k_final(const float4* __restrict__ x4,
                                               const float4* __restrict__ gamma4,
                                               const float4* __restrict__ beta4,
                                               float4* __restrict__ out4) {
    constexpr int P = 2;
    int warp = threadIdx.x >> 5, lane = threadIdx.x & 31;
    float4 m = g_mean4[lane];
    float m0 = __shfl_sync(0xffffffffu, m.x, 0);
    float inv1pm0 = 1.f / (1.f + m0);
    float mxs = (lane == 0) ? -m.x : m.x;
    float e0  = (lane == 0) ?  1.f : 0.f;

    // per-feature scale = gamma / (sqrt(var + eps) + eps)
    float4 g = gamma4[lane];
    float4 scl;
    {
        float gv[4] = {g.x, g.y, g.z, g.w};
        float sv[4];
#pragma unroll
        for (int j = 0; j < 4; j++) {
            int d = lane * 4 + j;
            float mv  = (float)(g_fs[d] * (1.0 / NPTS));
            float var = (float)(g_fq[d] * (1.0 / NPTS)) - mv * mv;
            float std = sqrtf(fmaxf(var, 0.f) + 1e-5f);
            sv[j] = gv[j] / (std + 1e-5f);
        }
        scl = make_float4(sv[0], sv[1], sv[2], sv[3]);
    }
    float4 be = beta4[lane];
    float b0 = __shfl_sync(0xffffffffu, be.x, 0);
    float inv1pb0 = 1.f / (1.f + b0);
    float bxs = (lane == 0) ? -be.x : be.x;

    int gw = blockIdx.x * 8 + warp;
    for (int p = gw; p < NPTS / P; p += NWTOT) {
        unsigned base = (unsigned)(p * P) * 32u + lane;
        const float4* ptr = x4 + base;
        float4 v[P];
#pragma unroll
        for (int i = 0; i < P; i++) v[i] = ptr[i * 32];
        xT_P<P>(v, m, mxs, m0, inv1pm0, e0);
#pragma unroll
        for (int i = 0; i < P; i++) {
            v[i].x *= scl.x; v[i].y *= scl.y; v[i].z *= scl.z; v[i].w *= scl.w;
        }
        // interleaved: euclid norm^2 (r[2i]) and linner(t, beta) (r[2i+1])
        float r[2 * P];
#pragma unroll
        for (int i = 0; i < P; i++) {
            float4 t = v[i];
            r[2*i]   = t.x*t.x + t.y*t.y + t.z*t.z + t.w*t.w;
            r[2*i+1] = t.x*bxs + t.y*be.y + t.z*be.z + t.w*be.w;
        }
        wsumP<2 * P>(r);
        float t0[P];
#pragma unroll
        for (int i = 0; i < P; i++) t0[i] = __shfl_sync(0xffffffffu, v[i].x, 0);
#pragma unroll
        for (int i = 0; i < P; i++) {
            float re = r[2*i], rb = r[2*i+1];
            float en   = sqrtf(re);
            float esc  = fminf(1.f, 32.f / fmaxf(en, 1e-8f));   // euclid cap
            float coef = esc * rb * inv1pb0;                    // transp0(beta)
            float4 t = v[i], w;
            w.x = fmaf(coef, be.x + e0, esc * t.x);
            w.y = fmaf(coef, be.y, esc * t.y);
            w.z = fmaf(coef, be.z, esc * t.z);
            w.w = fmaf(coef, be.w, esc * t.w);
            // linner(w,w) = esc^2 * (re - 2*t0^2)   (transport preserves norm)
            float q  = fmaxf(esc * esc * fmaf(-2.f * t0[i], t0[i], re), 1e-8f);
            float rq = rsqrtf(q);
            float nu = q * rq;                                   // sqrt(q)
            float ex  = __expf(nu);
            float exi = __expf(-nu);
            float ch  = 0.5f * (ex + exi);                       // cosh(nu)
            float shn = 0.5f * (ex - exi) * rq;                  // sinh(nu)/nu
            float4 o;
            o.x = fmaf(ch, be.x, shn * w.x);
            o.y = fmaf(ch, be.y, shn * w.y);
            o.z = fmaf(ch, be.z, shn * w.z);
            o.w = fmaf(ch, be.w, shn * w.w);
            __stcs(&out4[base + i * 32], o);
        }
    }
}

extern "C" void kernel_launch(void* const* d_in, const int* in_sizes, int n_in,
                              void* d_out, int out_size) {
    const float4* x  = (const float4*)d_in[0];
    const float4* ga = (const float4*)d_in[1];
    const float4* be = (const float4*)d_in[2];
    float4* out = (float4*)d_out;
    (void)in_sizes; (void)n_in; (void)out_size;

    k_init<<<8, 1024>>>();
    k_sumS<<<BB * CHUNKS, 256>>>(x);
    k_centroid<<<1, 1024>>>();
    k_stats<<<GRID_MAIN, 256>>>(x);
    k_final<<<GRID_MAIN, 256>>>(x, ga, be, out);
}

// round 4
// speedup vs baseline: 1.4997x; 1.1151x over previous
#include <cuda_runtime.h>

#define BB 64
#define SS 4096
#define DD 128
#define NPTS (BB*SS)
#define CHUNKS 16
#define PPB (SS/CHUNKS)
#define GRID_MAIN 592             // 4 blocks/SM * 148 SMs -> exactly one wave
#define NWTOT (GRID_MAIN * 8)     // warps in main kernels

// scratch (allocation-free rule: __device__ globals)
__device__ double g_sumB[BB*DD];   // per-(b,d) sums over S
__device__ float4 g_mean4[DD/4];   // global Lorentz centroid
__device__ double g_fs[DD];        // per-feature sum of x_T
__device__ double g_fq[DD];        // per-feature sum of x_T^2

__device__ __forceinline__ float wsum(float v) {
#pragma unroll
    for (int o = 16; o; o >>= 1) v += __shfl_xor_sync(0xffffffffu, v, o);
    return v;
}

template<int P>
__device__ __forceinline__ void wsumP(float* v) {
#pragma unroll
    for (int o = 16; o; o >>= 1) {
        float t[P];
#pragma unroll
        for (int i = 0; i < P; i++) t[i] = __shfl_xor_sync(0xffffffffu, v[i], o);
#pragma unroll
        for (int i = 0; i < P; i++) v[i] += t[i];
    }
}

__global__ void k_init() {
    int i = threadIdx.x + blockIdx.x * blockDim.x;
    for (int j = i; j < BB*DD; j += blockDim.x * gridDim.x) g_sumB[j] = 0.0;
    if (i < DD) { g_fs[i] = 0.0; g_fq[i] = 0.0; }
}

// Pass 1: sum over S per (b, d)
__global__ __launch_bounds__(256) void k_sumS(const float4* __restrict__ x4) {
    int b     = blockIdx.x >> 4;
    int chunk = blockIdx.x & 15;
    int warp = threadIdx.x >> 5, lane = threadIdx.x & 31;
    const float4* base = x4 + ((size_t)b * SS + (size_t)chunk * PPB) * 32 + lane;
    float4 acc = make_float4(0.f, 0.f, 0.f, 0.f);
#pragma unroll 4
    for (int s = warp; s < PPB; s += 8) {
        float4 v = base[(size_t)s * 32];
        acc.x += v.x; acc.y += v.y; acc.z += v.z; acc.w += v.w;
    }
    __shared__ float sh[8 * 128];
    int o = warp * 128 + lane * 4;
    sh[o] = acc.x; sh[o+1] = acc.y; sh[o+2] = acc.z; sh[o+3] = acc.w;
    __syncthreads();
    if (threadIdx.x < 128) {
        float v = 0.f;
#pragma unroll
        for (int w = 0; w < 8; w++) v += sh[w * 128 + threadIdx.x];
        atomicAdd(&g_sumB[b * 128 + threadIdx.x], (double)v);
    }
}

// Pass 2 (tiny): centroid of per-batch centroids
__global__ __launch_bounds__(1024) void k_centroid() {
    __shared__ float sh1[BB * DD];
    __shared__ float red[128];
    __shared__ float s_linner;
    int tid = threadIdx.x, warp = tid >> 5, lane = tid & 31;

#pragma unroll
    for (int rep = 0; rep < 2; rep++) {
        int b = warp + rep * 32;
        float a[4];
        float lc = 0.f;
#pragma unroll
        for (int j = 0; j < 4; j++) {
            a[j] = (float)(g_sumB[b * 128 + lane * 4 + j] * (1.0 / SS));
            float c = a[j] * a[j];
            if (lane == 0 && j == 0) c = -c;
            lc += c;
        }
        lc = wsum(lc);
        float denom = sqrtf(fmaxf(-lc, 1e-8f));
#pragma unroll
        for (int j = 0; j < 4; j++) sh1[b * 128 + lane * 4 + j] = a[j] / denom;
    }
    __syncthreads();

    float a2 = 0.f;
    if (tid < 128) {
        float s = 0.f;
        for (int b = 0; b < BB; b++) s += sh1[b * 128 + tid];
        a2 = s * (1.f / BB);
        float c = a2 * a2;
        red[tid] = (tid == 0) ? -c : c;
    }
    __syncthreads();
    for (int off = 64; off > 0; off >>= 1) {
        if (tid < off) red[tid] += red[tid + off];
        __syncthreads();
    }
    if (tid == 0) s_linner = red[0];
    __syncthreads();
    if (tid < 128) {
        float denom2 = sqrtf(fmaxf(-s_linner, 1e-8f));
        ((float*)g_mean4)[tid] = a2 / denom2;
    }
}

// x_T for P points: logmap at mean + transport to origin. ONE warp reduction.
// linner(u,u) = alpha^2 - 1 on the hyperboloid; acosh(a) = log(a+sqrt(a^2-1)).
// Also returns xt0[i] = time component of x_T (computable on all lanes).
template<int P>
__device__ __forceinline__ void xT_P(float4* v, float* xt0, const float4 m,
                                     const float mxs, const float m0,
                                     const float inv1pm0, const float e0) {
    float dp[P];
#pragma unroll
    for (int i = 0; i < P; i++)
        dp[i] = v[i].x*mxs + v[i].y*m.y + v[i].z*m.z + v[i].w*m.w;  // -> linner(x,m)
    wsumP<P>(dp);
    float x0[P];
#pragma unroll
    for (int i = 0; i < P; i++) x0[i] = __shfl_sync(0xffffffffu, v[i].x, 0);
#pragma unroll
    for (int i = 0; i < P; i++) {
        float alpha  = fmaxf(-dp[i], 1.0f + 1e-7f);
        float uu     = fmaf(alpha, alpha, -1.0f);           // linner(u,u)
        float runorm = rsqrtf(uu);
        float unorm  = uu * runorm;
        float fac    = __logf(alpha + unorm) * runorm;      // acosh(a)/|u|
        float u0     = fmaf(-alpha, m0, x0[i]);
        float coef   = -fac * u0 * inv1pm0;                 // transp0back
        float c2     = coef - fac * alpha;                  // t = fac*x + c2*m + coef*o
        float4 t;
        t.x = fmaf(fac, v[i].x, fmaf(c2, m.x, coef * e0));
        t.y = fmaf(fac, v[i].y, c2 * m.y);
        t.z = fmaf(fac, v[i].z, c2 * m.z);
        t.w = fmaf(fac, v[i].w, c2 * m.w);
        v[i] = t;
        xt0[i] = fmaf(fac, x0[i], fmaf(c2, m0, coef));      // time comp, all lanes
    }
}

// Pass 3: per-feature sum / sumsq of x_T (reverse sweep, prefetch pipeline)
__global__ __launch_bounds__(256) void k_stats(const float4* __restrict__ x4) {
    constexpr int P = 2;
    constexpr int PIT = NPTS / P;
    int warp = threadIdx.x >> 5, lane = threadIdx.x & 31;
    float4 m = g_mean4[lane];
    float m0 = __shfl_sync(0xffffffffu, m.x, 0);
    float inv1pm0 = 1.f / (1.f + m0);
    float mxs = (lane == 0) ? -m.x : m.x;
    float e0  = (lane == 0) ?  1.f : 0.f;
    float4 ss = make_float4(0,0,0,0), sq = make_float4(0,0,0,0);
    int gw = blockIdx.x * 8 + warp;

    int p = PIT - 1 - gw;                       // reverse sweep
    float4 v[P], vn[P];
    if (p >= 0) {
        unsigned b0i = (unsigned)p * (32u * P) + lane;
#pragma unroll
        for (int i = 0; i < P; i++) v[i] = x4[b0i + i * 32u];
    }
    while (p >= 0) {
        int pn = p - NWTOT;
        if (pn >= 0) {
            unsigned bni = (unsigned)pn * (32u * P) + lane;
#pragma unroll
            for (int i = 0; i < P; i++) vn[i] = x4[bni + i * 32u];
        }
        float xt0[P];
        xT_P<P>(v, xt0, m, mxs, m0, inv1pm0, e0);
#pragma unroll
        for (int i = 0; i < P; i++) {
            ss.x += v[i].x; ss.y += v[i].y; ss.z += v[i].z; ss.w += v[i].w;
            sq.x = fmaf(v[i].x, v[i].x, sq.x); sq.y = fmaf(v[i].y, v[i].y, sq.y);
            sq.z = fmaf(v[i].z, v[i].z, sq.z); sq.w = fmaf(v[i].w, v[i].w, sq.w);
        }
#pragma unroll
        for (int i = 0; i < P; i++) v[i] = vn[i];
        p = pn;
    }
    __shared__ float shs[8 * 128];
    __shared__ float shq[8 * 128];
    int o = warp * 128 + lane * 4;
    shs[o]=ss.x; shs[o+1]=ss.y; shs[o+2]=ss.z; shs[o+3]=ss.w;
    shq[o]=sq.x; shq[o+1]=sq.y; shq[o+2]=sq.z; shq[o+3]=sq.w;
    __syncthreads();
    if (threadIdx.x < 128) {
        float a = 0.f, b = 0.f;
#pragma unroll
        for (int w = 0; w < 8; w++) { a += shs[w*128 + threadIdx.x]; b += shq[w*128 + threadIdx.x]; }
        atomicAdd(&g_fs[threadIdx.x], (double)a);
        atomicAdd(&g_fq[threadIdx.x], (double)b);
    }
}

// Pass 4: scale, rescale-to-max-euclid, transp0(beta), expmap(beta).
// Transport preserves linner; if beta == origin, linner(t,beta) = -t0 (no reduction).
__global__ __launch_bounds__(256) void k_final(const float4* __restrict__ x4,
                                               const float4* __restrict__ gamma4,
                                               const float4* __restrict__ beta4,
                                               float4* __restrict__ out4) {
    constexpr int P = 2;
    constexpr int PIT = NPTS / P;
    int warp = threadIdx.x >> 5, lane = threadIdx.x & 31;
    float4 m = g_mean4[lane];
    float m0 = __shfl_sync(0xffffffffu, m.x, 0);
    float inv1pm0 = 1.f / (1.f + m0);
    float mxs = (lane == 0) ? -m.x : m.x;
    float e0  = (lane == 0) ?  1.f : 0.f;

    // per-feature scale = gamma / (sqrt(var + eps) + eps)
    float4 g = gamma4[lane];
    float4 scl;
    {
        float gv[4] = {g.x, g.y, g.z, g.w};
        float sv[4];
#pragma unroll
        for (int j = 0; j < 4; j++) {
            int d = lane * 4 + j;
            float mv  = (float)(g_fs[d] * (1.0 / NPTS));
            float var = (float)(g_fq[d] * (1.0 / NPTS)) - mv * mv;
            float std = sqrtf(fmaxf(var, 0.f) + 1e-5f);
            sv[j] = gv[j] / (std + 1e-5f);
        }
        scl = make_float4(sv[0], sv[1], sv[2], sv[3]);
    }
    float scl0 = __shfl_sync(0xffffffffu, scl.x, 0);

    float4 be = beta4[lane];
    float b0 = __shfl_sync(0xffffffffu, be.x, 0);
    float inv1pb0 = 1.f / (1.f + b0);
    float bxs = (lane == 0) ? -be.x : be.x;
    // uniform runtime check: beta == manifold origin (1, 0, ..., 0)?
    float bsq = wsum(be.x*be.x + be.y*be.y + be.z*be.z + be.w*be.w);
    bool is_origin = (b0 == 1.0f) && (bsq - b0 * b0 <= 0.0f);

    int gw = blockIdx.x * 8 + warp;
    int p = gw;                                  // forward sweep (hits k_stats' L2 tail)
    float4 v[P], vn[P];
    if (p < PIT) {
        unsigned b0i = (unsigned)p * (32u * P) + lane;
#pragma unroll
        for (int i = 0; i < P; i++) v[i] = __ldcs(&x4[b0i + i * 32u]);
    }
    while (p < PIT) {
        int pn = p + NWTOT;
        if (pn < PIT) {
            unsigned bni = (unsigned)pn * (32u * P) + lane;
#pragma unroll
            for (int i = 0; i < P; i++) vn[i] = __ldcs(&x4[bni + i * 32u]);
        }
        float xt0[P];
        xT_P<P>(v, xt0, m, mxs, m0, inv1pm0, e0);
        float t0[P], re[P], rb[P];
#pragma unroll
        for (int i = 0; i < P; i++) {
            v[i].x *= scl.x; v[i].y *= scl.y; v[i].z *= scl.z; v[i].w *= scl.w;
            t0[i] = scl0 * xt0[i];
            float4 t = v[i];
            re[i] = t.x*t.x + t.y*t.y + t.z*t.z + t.w*t.w;     // euclid norm^2
        }
        if (is_origin) {
            wsumP<P>(re);
#pragma unroll
            for (int i = 0; i < P; i++) rb[i] = -t0[i];         // linner(t, origin)
        } else {
            float r2[2 * P];
#pragma unroll
            for (int i = 0; i < P; i++) {
                float4 t = v[i];
                r2[2*i]   = re[i];
                r2[2*i+1] = t.x*bxs + t.y*be.y + t.z*be.z + t.w*be.w;
            }
            wsumP<2 * P>(r2);
#pragma unroll
            for (int i = 0; i < P; i++) { re[i] = r2[2*i]; rb[i] = r2[2*i+1]; }
        }
        unsigned bso = (unsigned)p * (32u * P) + lane;
#pragma unroll
        for (int i = 0; i < P; i++) {
            float en   = sqrtf(re[i]);
            float esc  = fminf(1.f, 32.f / fmaxf(en, 1e-8f));   // euclid cap
            float coef = esc * rb[i] * inv1pb0;                 // transp0(beta)
            float4 t = v[i], w;
            w.x = fmaf(coef, be.x + e0, esc * t.x);
            w.y = fmaf(coef, be.y, esc * t.y);
            w.z = fmaf(coef, be.z, esc * t.z);
            w.w = fmaf(coef, be.w, esc * t.w);
            // linner(w,w) = esc^2 * (re - 2*t0^2)  (transport preserves norm)
            float q  = fmaxf(esc * esc * fmaf(-2.f * t0[i], t0[i], re[i]), 1e-8f);
            float rq = rsqrtf(q);
            float nu = q * rq;                                  // sqrt(q)
            float ex  = __expf(nu);
            float exi = __expf(-nu);
            float ch  = 0.5f * (ex + exi);                      // cosh
            float shn = 0.5f * (ex - exi) * rq;                 // sinh(nu)/nu
            float4 o;
            o.x = fmaf(ch, be.x, shn * w.x);
            o.y = fmaf(ch, be.y, shn * w.y);
            o.z = fmaf(ch, be.z, shn * w.z);
            o.w = fmaf(ch, be.w, shn * w.w);
            __stcs(&out4[bso + i * 32u], o);
        }
#pragma unroll
        for (int i = 0; i < P; i++) v[i] = vn[i];
        p = pn;
    }
}

extern "C" void kernel_launch(void* const* d_in, const int* in_sizes, int n_in,
                              void* d_out, int out_size) {
    const float4* x  = (const float4*)d_in[0];
    const float4* ga = (const float4*)d_in[1];
    const float4* be = (const float4*)d_in[2];
    float4* out = (float4*)d_out;
    (void)in_sizes; (void)n_in; (void)out_size;

    k_init<<<8, 1024>>>();
    k_sumS<<<BB * CHUNKS, 256>>>(x);
    k_centroid<<<1, 1024>>>();
    k_stats<<<GRID_MAIN, 256>>>(x);
    k_final<<<GRID_MAIN, 256>>>(x, ga, be, out);
}

// round 5
// speedup vs baseline: 1.5217x; 1.0147x over previous
#include <cuda_runtime.h>

#define BB 64
#define SS 4096
#define DD 128
#define NPTS (BB*SS)
#define CHUNKS 16
#define PPB (SS/CHUNKS)
#define GRID_STATS 888            // 6 blocks/SM * 148 SMs, one wave
#define NW_STATS (GRID_STATS * 8)
#define GRID_FIN 592              // 4 blocks/SM * 148 SMs, one wave
#define NW_FIN (GRID_FIN * 8)

// scratch (allocation-free rule: __device__ globals)
__device__ float  g_part[CHUNKS*BB*DD]; // per-(chunk,b,d) partial sums (no init needed)
__device__ float4 g_mean4[DD/4];        // global Lorentz centroid
__device__ double g_fs[DD];             // per-feature sum of x_T
__device__ double g_fq[DD];             // per-feature sum of x_T^2

__device__ __forceinline__ float wsum(float v) {
#pragma unroll
    for (int o = 16; o; o >>= 1) v += __shfl_xor_sync(0xffffffffu, v, o);
    return v;
}

template<int P>
__device__ __forceinline__ void wsumP(float* v) {
#pragma unroll
    for (int o = 16; o; o >>= 1) {
        float t[P];
#pragma unroll
        for (int i = 0; i < P; i++) t[i] = __shfl_xor_sync(0xffffffffu, v[i], o);
#pragma unroll
        for (int i = 0; i < P; i++) v[i] += t[i];
    }
}

// Pass 1: per-(b,chunk) sums over 256 points -> g_part (no atomics, no init)
__global__ __launch_bounds__(256) void k_sumS(const float4* __restrict__ x4) {
    int b     = blockIdx.x >> 4;
    int chunk = blockIdx.x & 15;
    int warp = threadIdx.x >> 5, lane = threadIdx.x & 31;
    const float4* base = x4 + ((size_t)b * SS + (size_t)chunk * PPB) * 32 + lane;
    float4 acc = make_float4(0.f, 0.f, 0.f, 0.f);
#pragma unroll 4
    for (int s = warp; s < PPB; s += 8) {
        float4 v = base[(size_t)s * 32];
        acc.x += v.x; acc.y += v.y; acc.z += v.z; acc.w += v.w;
    }
    __shared__ float sh[8 * 128];
    int o = warp * 128 + lane * 4;
    sh[o] = acc.x; sh[o+1] = acc.y; sh[o+2] = acc.z; sh[o+3] = acc.w;
    __syncthreads();
    if (threadIdx.x < 128) {
        float v = 0.f;
#pragma unroll
        for (int w = 0; w < 8; w++) v += sh[w * 128 + threadIdx.x];
        g_part[(chunk * BB + b) * DD + threadIdx.x] = v;
    }
}

// Pass 2 (tiny): reduce partials, centroid of per-batch centroids, zero stats
__global__ __launch_bounds__(1024) void k_centroid() {
    __shared__ float sh1[BB * DD];
    __shared__ float red[128];
    __shared__ float s_linner;
    int tid = threadIdx.x, warp = tid >> 5, lane = tid & 31;

    // phase 1: sum the 16 chunk partials for each (b,d)
    for (int idx = tid; idx < BB*DD; idx += 1024) {
        float s = 0.f;
#pragma unroll
        for (int c = 0; c < CHUNKS; c++) s += g_part[c * BB * DD + idx];
        sh1[idx] = s;
    }
    if (tid < DD) { g_fs[tid] = 0.0; g_fq[tid] = 0.0; }
    __syncthreads();

    // phase 2: normalize each batch-mean onto the hyperboloid
#pragma unroll
    for (int rep = 0; rep < 2; rep++) {
        int b = warp + rep * 32;
        float a[4];
        float lc = 0.f;
#pragma unroll
        for (int j = 0; j < 4; j++) {
            a[j] = sh1[b * 128 + lane * 4 + j] * (1.f / SS);
            float c = a[j] * a[j];
            if (lane == 0 && j == 0) c = -c;
            lc += c;
        }
        lc = wsum(lc);
        float denom = sqrtf(fmaxf(-lc, 1e-8f));
#pragma unroll
        for (int j = 0; j < 4; j++) sh1[b * 128 + lane * 4 + j] = a[j] / denom;
    }
    __syncthreads();

    // phase 3: mean of the 64 centroids, renormalize
    float a2 = 0.f;
    if (tid < 128) {
        float s = 0.f;
        for (int b = 0; b < BB; b++) s += sh1[b * 128 + tid];
        a2 = s * (1.f / BB);
        float c = a2 * a2;
        red[tid] = (tid == 0) ? -c : c;
    }
    __syncthreads();
    for (int off = 64; off > 0; off >>= 1) {
        if (tid < off) red[tid] += red[tid + off];
        __syncthreads();
    }
    if (tid == 0) s_linner = red[0];
    __syncthreads();
    if (tid < 128) {
        float denom2 = sqrtf(fmaxf(-s_linner, 1e-8f));
        ((float*)g_mean4)[tid] = a2 / denom2;
    }
}

// x_T for P points: logmap at mean + transport to origin. ONE warp reduction.
// Identities: linner(u,u) = alpha^2 - 1; acosh(a) = log(a + sqrt(a^2-1));
// time component of result is identically 0 (tangent at origin).
template<int P>
__device__ __forceinline__ void xT_P(float4* v, const float4 m, const float mxs,
                                     const float m0, const float inv1pm0,
                                     const float e0) {
    float dp[P];
#pragma unroll
    for (int i = 0; i < P; i++)
        dp[i] = v[i].x*mxs + v[i].y*m.y + v[i].z*m.z + v[i].w*m.w;  // -> linner(x,m)
    wsumP<P>(dp);
    float x0[P];
#pragma unroll
    for (int i = 0; i < P; i++) x0[i] = __shfl_sync(0xffffffffu, v[i].x, 0);
#pragma unroll
    for (int i = 0; i < P; i++) {
        float alpha  = fmaxf(-dp[i], 1.0f + 1e-7f);
        float uu     = fmaf(alpha, alpha, -1.0f);           // linner(u,u)
        float runorm = rsqrtf(uu);
        float unorm  = uu * runorm;
        float fac    = __logf(alpha + unorm) * runorm;      // acosh(a)/|u|
        float u0     = fmaf(-alpha, m0, x0[i]);
        float coef   = -fac * u0 * inv1pm0;                 // transp0back
        float c2     = fmaf(-fac, alpha, coef);             // t = fac*x + c2*m + coef*o
        float4 t;
        t.x = fmaf(fac, v[i].x, fmaf(c2, m.x, coef * e0));
        t.y = fmaf(fac, v[i].y, c2 * m.y);
        t.z = fmaf(fac, v[i].z, c2 * m.z);
        t.w = fmaf(fac, v[i].w, c2 * m.w);
        v[i] = t;
    }
}

// Pass 3: per-feature sum / sumsq of x_T (reverse sweep, 6 blocks/SM)
__global__ __launch_bounds__(256, 6) void k_stats(const float4* __restrict__ x4) {
    constexpr int P = 2;
    constexpr int PIT = NPTS / P;
    int warp = threadIdx.x >> 5, lane = threadIdx.x & 31;
    float4 m = g_mean4[lane];
    float m0 = __shfl_sync(0xffffffffu, m.x, 0);
    float inv1pm0 = 1.f / (1.f + m0);
    float mxs = (lane == 0) ? -m.x : m.x;
    float e0  = (lane == 0) ?  1.f : 0.f;
    float4 ss = make_float4(0,0,0,0), sq = make_float4(0,0,0,0);
    int gw = blockIdx.x * 8 + warp;

    for (int p = PIT - 1 - gw; p >= 0; p -= NW_STATS) {   // reverse sweep
        unsigned bi = (unsigned)p * 64u + lane;
        float4 v[P];
        v[0] = x4[bi];
        v[1] = x4[bi + 32u];
        xT_P<P>(v, m, mxs, m0, inv1pm0, e0);
#pragma unroll
        for (int i = 0; i < P; i++) {
            ss.x += v[i].x; ss.y += v[i].y; ss.z += v[i].z; ss.w += v[i].w;
            sq.x = fmaf(v[i].x, v[i].x, sq.x); sq.y = fmaf(v[i].y, v[i].y, sq.y);
            sq.z = fmaf(v[i].z, v[i].z, sq.z); sq.w = fmaf(v[i].w, v[i].w, sq.w);
        }
    }
    __shared__ float shs[8 * 128];
    __shared__ float shq[8 * 128];
    int o = warp * 128 + lane * 4;
    shs[o]=ss.x; shs[o+1]=ss.y; shs[o+2]=ss.z; shs[o+3]=ss.w;
    shq[o]=sq.x; shq[o+1]=sq.y; shq[o+2]=sq.z; shq[o+3]=sq.w;
    __syncthreads();
    if (threadIdx.x < 128) {
        float a = 0.f, b = 0.f;
#pragma unroll
        for (int w = 0; w < 8; w++) { a += shs[w*128 + threadIdx.x]; b += shq[w*128 + threadIdx.x]; }
        atomicAdd(&g_fs[threadIdx.x], (double)a);
        atomicAdd(&g_fq[threadIdx.x], (double)b);
    }
}

// Pass 4: scale, euclid cap, transp0(beta), expmap(beta).
// t0 == 0 identically => linner(w,w) = esc^2 * re; beta==origin => transp0 = identity.
__global__ __launch_bounds__(256) void k_final(const float4* __restrict__ x4,
                                               const float4* __restrict__ gamma4,
                                               const float4* __restrict__ beta4,
                                               float4* __restrict__ out4) {
    constexpr int P = 2;
    constexpr int PIT = NPTS / P;
    int warp = threadIdx.x >> 5, lane = threadIdx.x & 31;
    float4 m = g_mean4[lane];
    float m0 = __shfl_sync(0xffffffffu, m.x, 0);
    float inv1pm0 = 1.f / (1.f + m0);
    float mxs = (lane == 0) ? -m.x : m.x;
    float e0  = (lane == 0) ?  1.f : 0.f;

    // per-feature scale = gamma / (sqrt(var + eps) + eps)
    float4 g = gamma4[lane];
    float4 scl;
    {
        float gv[4] = {g.x, g.y, g.z, g.w};
        float sv[4];
#pragma unroll
        for (int j = 0; j < 4; j++) {
            int d = lane * 4 + j;
            float mv  = (float)(g_fs[d] * (1.0 / NPTS));
            float var = (float)(g_fq[d] * (1.0 / NPTS)) - mv * mv;
            float std = sqrtf(fmaxf(var, 0.f) + 1e-5f);
            sv[j] = gv[j] / (std + 1e-5f);
        }
        scl = make_float4(sv[0], sv[1], sv[2], sv[3]);
    }

    float4 be = beta4[lane];
    float b0 = __shfl_sync(0xffffffffu, be.x, 0);
    float inv1pb0 = 1.f / (1.f + b0);
    float bxs = (lane == 0) ? -be.x : be.x;
    // uniform runtime check: beta == manifold origin (1, 0, ..., 0)?
    float bsq = wsum(be.x*be.x + be.y*be.y + be.z*be.z + be.w*be.w);
    bool is_origin = (b0 == 1.0f) && (bsq - b0 * b0 <= 0.0f);

    int gw = blockIdx.x * 8 + warp;
    int p = gw;                                  // forward sweep (hits k_stats' L2 tail)
    float4 v[P], vn[P];
    if (p < PIT) {
        unsigned bi = (unsigned)p * 64u + lane;
        v[0] = __ldcs(&x4[bi]); v[1] = __ldcs(&x4[bi + 32u]);
    }
    while (p < PIT) {
        int pn = p + NW_FIN;
        if (pn < PIT) {
            unsigned bni = (unsigned)pn * 64u + lane;
            vn[0] = __ldcs(&x4[bni]); vn[1] = __ldcs(&x4[bni + 32u]);
        }
        xT_P<P>(v, m, mxs, m0, inv1pm0, e0);
        float re[P];
#pragma unroll
        for (int i = 0; i < P; i++) {
            v[i].x *= scl.x; v[i].y *= scl.y; v[i].z *= scl.z; v[i].w *= scl.w;
            float4 t = v[i];
            re[i] = t.x*t.x + t.y*t.y + t.z*t.z + t.w*t.w;     // euclid norm^2
        }
        unsigned bso = (unsigned)p * 64u + lane;
        if (is_origin) {
            wsumP<P>(re);
#pragma unroll
            for (int i = 0; i < P; i++) {
                float rre = fmaxf(re[i], 1e-8f);
                float rq  = rsqrtf(rre);
                float en  = rre * rq;                  // ||t||
                float nu  = fminf(en, 32.f);           // esc * ||t||
                float ex  = __expf(nu);
                float exi = __expf(-nu);
                float ch  = 0.5f * (ex + exi);
                float sf  = 0.5f * (ex - exi) / en;    // sinh(nu)/||t|| = esc*sinh(nu)/nu
                float4 t = v[i], o;
                o.x = fmaf(sf, t.x, ch * e0);
                o.y = sf * t.y;
                o.z = sf * t.z;
                o.w = sf * t.w;
                __stcs(&out4[bso + (unsigned)i * 32u], o);
            }
        } else {
            float r2[2 * P];
#pragma unroll
            for (int i = 0; i < P; i++) {
                float4 t = v[i];
                r2[2*i]   = re[i];
                r2[2*i+1] = t.x*bxs + t.y*be.y + t.z*be.z + t.w*be.w;  // linner(t,be)
            }
            wsumP<2 * P>(r2);
#pragma unroll
            for (int i = 0; i < P; i++) {
                float rre = fmaxf(r2[2*i], 1e-8f);
                float rq  = rsqrtf(rre);
                float esc = fminf(1.f, 32.f * rq);     // euclid cap
                float coef = esc * r2[2*i+1] * inv1pb0;
                float4 t = v[i], w;
                w.x = fmaf(coef, be.x + e0, esc * t.x);
                w.y = fmaf(coef, be.y, esc * t.y);
                w.z = fmaf(coef, be.z, esc * t.z);
                w.w = fmaf(coef, be.w, esc * t.w);
                // linner(w,w) = esc^2 * re  (t0 == 0, transport preserves norm)
                float nu  = fminf(rre * rq, 32.f);     // esc*sqrt(re), clamped form
                float rnu = fmaxf(nu, 1e-4f);
                float ex  = __expf(rnu);
                float exi = __expf(-rnu);
                float ch  = 0.5f * (ex + exi);
                float shn = 0.5f * (ex - exi) / rnu;
                float4 o;
                o.x = fmaf(ch, be.x, shn * w.x);
                o.y = fmaf(ch, be.y, shn * w.y);
                o.z = fmaf(ch, be.z, shn * w.z);
                o.w = fmaf(ch, be.w, shn * w.w);
                __stcs(&out4[bso + (unsigned)i * 32u], o);
            }
        }
        v[0] = vn[0]; v[1] = vn[1];
        p = pn;
    }
}

extern "C" void kernel_launch(void* const* d_in, const int* in_sizes, int n_in,
                              void* d_out, int out_size) {
    const float4* x  = (const float4*)d_in[0];
    const float4* ga = (const float4*)d_in[1];
    const float4* be = (const float4*)d_in[2];
    float4* out = (float4*)d_out;
    (void)in_sizes; (void)n_in; (void)out_size;

    k_sumS<<<BB * CHUNKS, 256>>>(x);
    k_centroid<<<1, 1024>>>();
    k_stats<<<GRID_STATS, 256>>>(x);
    k_final<<<GRID_FIN, 256>>>(x, ga, be, out);
}